// round 3
// baseline (speedup 1.0000x reference)
#include <cuda_runtime.h>
#include <math.h>
#include <stdint.h>

#define DIMV 128

static const long V  = 50000;
static const long C  = 150000;
static const long EP = 200000;
static const long EN = 200000;
static const int  NITER = 4;

// ---------------- scratch layout (floats) ----------------
#define O_MSG_PV2C 0L
#define O_MSG_NV2C (O_MSG_PV2C + V*DIMV)
#define O_MSG_PC2V (O_MSG_NV2C + V*DIMV)
#define O_MSG_NC2V (O_MSG_PC2V + C*DIMV)
#define O_HID      (O_MSG_NC2V + C*DIMV)
#define O_AGG_PC   (O_HID + C*DIMV)
#define O_AGG_NC   (O_AGG_PC + C*DIMV)
#define O_AGG_PV   (O_AGG_NC + C*DIMV)
#define O_AGG_NV   (O_AGG_PV + V*DIMV)
#define O_DEG_PV   (O_AGG_NV + V*DIMV)
#define O_DEG_NV   (O_DEG_PV + V)
#define O_DEG_PC   (O_DEG_NV + V)
#define O_DEG_NC   (O_DEG_PC + C)
#define O_PNORM    (O_DEG_NC + C)
#define O_NNORM    (O_PNORM + EP)
#define O_IDX      (O_NNORM + EN)
#define SCRATCH_TOTAL (O_IDX + 2*EP + 2*EN)

__device__ float g_scratch[SCRATCH_TOTAL];

// ---------------- small kernels ----------------

__global__ void deg_kernel(const int* __restrict__ ev, const int* __restrict__ ec,
                           const int* __restrict__ sel, int nE,
                           float* __restrict__ degv, float* __restrict__ degc,
                           int* __restrict__ outv, int* __restrict__ outc)
{
    int e = blockIdx.x * blockDim.x + threadIdx.x;
    if (e >= nE) return;
    int ed = sel[e];
    int v = ev[ed], c = ec[ed];
    outv[e] = v; outc[e] = c;
    atomicAdd(&degv[v], 1.0f);
    atomicAdd(&degc[c], 1.0f);
}

__global__ void norm_kernel(const int* __restrict__ iv, const int* __restrict__ ic,
                            const float* __restrict__ degv, const float* __restrict__ degc,
                            float* __restrict__ ninv, int nE)
{
    int e = blockIdx.x * blockDim.x + threadIdx.x;
    if (e >= nE) return;
    float dv = fmaxf(degv[iv[e]], 1.0f);
    float dc = fmaxf(degc[ic[e]], 1.0f);
    ninv[e] = 1.0f / (sqrtf(dv) * sqrtf(dc));
}

__device__ __forceinline__ void red_add_v4(float* addr, float4 v)
{
    asm volatile("red.global.add.v4.f32 [%0], {%1,%2,%3,%4};"
                 :: "l"(addr), "f"(v.x), "f"(v.y), "f"(v.z), "f"(v.w) : "memory");
}
__device__ __forceinline__ void red_add_v2(float* addr, float a, float b)
{
    asm volatile("red.global.add.v2.f32 [%0], {%1,%2};"
                 :: "l"(addr), "f"(a), "f"(b) : "memory");
}

// one warp per edge: gather msg rows for both directions, scale, vector-reduce.
__global__ void scatter_kernel(const int* __restrict__ si, const int* __restrict__ di,
                               const float* __restrict__ msgS, const float* __restrict__ msgD,
                               const float* __restrict__ ninv,
                               float* __restrict__ aggD, float* __restrict__ aggS, int nE)
{
    int w = (blockIdx.x * blockDim.x + threadIdx.x) >> 5;
    int lane = threadIdx.x & 31;
    if (w >= nE) return;
    int s = si[w];
    int d = di[w];
    float nv = ninv[w];
    float4 a = ((const float4*)(msgS + (long)s * DIMV))[lane];
    float4 b = ((const float4*)(msgD + (long)d * DIMV))[lane];
    a.x *= nv; a.y *= nv; a.z *= nv; a.w *= nv;
    b.x *= nv; b.y *= nv; b.z *= nv; b.w *= nv;
    red_add_v4(aggD + (long)d * DIMV + lane * 4, a);
    red_add_v4(aggS + (long)s * DIMV + lane * 4, b);
}

// ---------------- TF32 tensor-core GEMM ----------------
// out[N,128] = X[N,128] @ W[128,128]
// MODE 0: relu(X@W+bias) store   MODE 1: X@W+bias store   MODE 2: red.add(out, X@W)
//
// CTA tile: 128 rows x 128 cols, 256 threads (8 warps, 4x2 warp grid,
// warp tile 32x64). X and W are converted to tf32 and pre-permuted into
// exact m16n8k8 fragment layout in smem, so mainloop fragment loads are
// conflict-free LDS.128 / LDS.64.

__device__ __forceinline__ uint32_t f2tf32(float f)
{
    uint32_t t;
    asm("cvt.rna.tf32.f32 %0, %1;" : "=r"(t) : "f"(f));
    return t;
}

__device__ __forceinline__ void mma_tf32(float* c, const uint32_t* a, uint32_t b0, uint32_t b1)
{
    asm volatile("mma.sync.aligned.m16n8k8.row.col.f32.tf32.tf32.f32 "
                 "{%0,%1,%2,%3}, {%4,%5,%6,%7}, {%8,%9}, {%0,%1,%2,%3};"
                 : "+f"(c[0]), "+f"(c[1]), "+f"(c[2]), "+f"(c[3])
                 : "r"(a[0]), "r"(a[1]), "r"(a[2]), "r"(a[3]), "r"(b0), "r"(b1));
}

#define GEMM_SMEM (2 * 16384 * 4)   // As + Bs, 128 KB

template<int MODE>
__global__ __launch_bounds__(256)
void gemm_tf32_kernel(const float* __restrict__ X, const float* __restrict__ W,
                      const float* __restrict__ bias, float* __restrict__ out, int N)
{
    extern __shared__ uint32_t sm[];
    uint32_t* As = sm;            // [kstep 16][mtile 8][lane 32][reg 4]
    uint32_t* Bs = sm + 16384;    // [kstep 16][ntile 16][lane 32][reg 2]

    const int tid = threadIdx.x;
    const long row0 = (long)blockIdx.x * 128;

    // ---- W -> Bs fragment layout (b0: k=l%4, n=l/4 ; b1: k=l%4+4) ----
    const float4* Wg = (const float4*)W;
    #pragma unroll
    for (int i = 0; i < 16; i++) {
        int idx = tid + i * 256;          // 0..4095
        int k = idx >> 5;
        int n0 = (idx & 31) * 4;
        float4 v = Wg[idx];
        int kstep = k >> 3, kk = k & 7;
        int reg = kk >> 2;                // 0/1
        int klane = kk & 3;
        float vv[4] = {v.x, v.y, v.z, v.w};
        #pragma unroll
        for (int j = 0; j < 4; j++) {
            int n = n0 + j;
            int ntile = n >> 3, nn = n & 7;
            int lane = nn * 4 + klane;
            Bs[((kstep * 16 + ntile) * 32 + lane) * 2 + reg] = f2tf32(vv[j]);
        }
    }

    // ---- X tile -> As fragment layout ----
    // a-reg: reg = (rr/8) + 2*(k>=4), lane = (rr%8)*4 + k%4
    const float4* Xg = (const float4*)X;
    #pragma unroll
    for (int i = 0; i < 16; i++) {
        int idx = tid + i * 256;
        int r = idx >> 5;
        int c4 = idx & 31;
        int col = c4 * 4;
        long rr_g = row0 + r;
        float4 v = make_float4(0.f, 0.f, 0.f, 0.f);
        if (rr_g < N) v = Xg[rr_g * 32 + c4];
        int kstep = col >> 3;
        int cc = col & 7;                 // 0 or 4
        int mtile = r >> 4, rr = r & 15;
        int lanebase = (rr & 7) * 4;
        int reg = (rr >> 3) + 2 * (cc >> 2);
        float vv[4] = {v.x, v.y, v.z, v.w};
        uint32_t* dst = &As[(kstep * 8 + mtile) * 128 + reg];
        #pragma unroll
        for (int j = 0; j < 4; j++)
            dst[(lanebase + j) * 4] = f2tf32(vv[j]);
    }
    __syncthreads();

    // ---- mainloop ----
    const int w = tid >> 5, lane = tid & 31;
    const int wr = w >> 1, wc = w & 1;

    float acc[2][8][4];
    #pragma unroll
    for (int mi = 0; mi < 2; mi++)
        #pragma unroll
        for (int ni = 0; ni < 8; ni++)
            #pragma unroll
            for (int q = 0; q < 4; q++) acc[mi][ni][q] = 0.f;

    #pragma unroll 4
    for (int ks = 0; ks < 16; ks++) {
        uint4 a[2];
        #pragma unroll
        for (int mi = 0; mi < 2; mi++)
            a[mi] = ((const uint4*)As)[(ks * 8 + (wr * 2 + mi)) * 32 + lane];
        #pragma unroll
        for (int ni = 0; ni < 8; ni++) {
            uint2 b = ((const uint2*)Bs)[(ks * 16 + (wc * 8 + ni)) * 32 + lane];
            mma_tf32(acc[0][ni], (const uint32_t*)&a[0], b.x, b.y);
            mma_tf32(acc[1][ni], (const uint32_t*)&a[1], b.x, b.y);
        }
    }

    // ---- epilogue ----
    const int q = lane >> 2, t = lane & 3;
    #pragma unroll
    for (int mi = 0; mi < 2; mi++) {
        #pragma unroll
        for (int h = 0; h < 2; h++) {
            long rg = row0 + wr * 32 + mi * 16 + h * 8 + q;
            if (rg >= N) continue;
            #pragma unroll
            for (int ni = 0; ni < 8; ni++) {
                int colg = wc * 64 + ni * 8 + t * 2;
                float o0 = acc[mi][ni][h * 2 + 0];
                float o1 = acc[mi][ni][h * 2 + 1];
                if (MODE == 2) {
                    red_add_v2(out + rg * DIMV + colg, o0, o1);
                } else {
                    o0 += bias[colg];
                    o1 += bias[colg + 1];
                    if (MODE == 0) { o0 = fmaxf(o0, 0.f); o1 = fmaxf(o1, 0.f); }
                    float2 ov = make_float2(o0, o1);
                    *(float2*)(out + rg * DIMV + colg) = ov;
                }
            }
        }
    }
}

// ---------------- host side ----------------

static void gemm(int mode, const float* X, const float* W, const float* bias,
                 float* out, long N)
{
    dim3 grid((unsigned)((N + 127) / 128));
    if (mode == 0)      gemm_tf32_kernel<0><<<grid, 256, GEMM_SMEM>>>(X, W, bias, out, (int)N);
    else if (mode == 1) gemm_tf32_kernel<1><<<grid, 256, GEMM_SMEM>>>(X, W, bias, out, (int)N);
    else                gemm_tf32_kernel<2><<<grid, 256, GEMM_SMEM>>>(X, W, bias, out, (int)N);
}

extern "C" void kernel_launch(void* const* d_in, const int* in_sizes, int n_in,
                              void* d_out, int out_size)
{
    const int ofs = n_in - 14;
    const int*   v_edge = (const int*)d_in[ofs + 0];
    const int*   c_edge = (const int*)d_in[ofs + 1];
    const int*   p_sel  = (const int*)d_in[ofs + 2];
    const int*   n_sel  = (const int*)d_in[ofs + 3];
    const float* v_emb0 = (const float*)d_in[ofs + 4];
    const float* c_emb0 = (const float*)d_in[ofs + 5];
    const float* W1     = (const float*)d_in[ofs + 6];
    const float* b1     = (const float*)d_in[ofs + 7];
    const float* W2     = (const float*)d_in[ofs + 8];
    const float* b2     = (const float*)d_in[ofs + 9];
    const float* cW     = (const float*)d_in[ofs + 10];
    const float* cB     = (const float*)d_in[ofs + 11];
    const float* vW     = (const float*)d_in[ofs + 12];
    const float* vB     = (const float*)d_in[ofs + 13];

    float* base = nullptr;
    cudaGetSymbolAddress((void**)&base, g_scratch);

    float* msgPV2C = base + O_MSG_PV2C;
    float* msgNV2C = base + O_MSG_NV2C;
    float* msgPC2V = base + O_MSG_PC2V;
    float* msgNC2V = base + O_MSG_NC2V;
    float* hid     = base + O_HID;
    float* aggPC   = base + O_AGG_PC;
    float* aggNC   = base + O_AGG_NC;
    float* aggPV   = base + O_AGG_PV;
    float* aggNV   = base + O_AGG_NV;
    float* degPV   = base + O_DEG_PV;
    float* degNV   = base + O_DEG_NV;
    float* degPC   = base + O_DEG_PC;
    float* degNC   = base + O_DEG_NC;
    float* pnorm   = base + O_PNORM;
    float* nnorm   = base + O_NNORM;
    int*   pv      = (int*)(base + O_IDX);
    int*   pc      = pv + EP;
    int*   nv      = pc + EP;
    int*   nc      = nv + EN;

    float* out = (float*)d_out;
    float* OV = out;                    // [5][V][128]
    float* OC = out + 5L * V * DIMV;    // [5][C][128]

    cudaFuncSetAttribute(gemm_tf32_kernel<0>, cudaFuncAttributeMaxDynamicSharedMemorySize, GEMM_SMEM);
    cudaFuncSetAttribute(gemm_tf32_kernel<1>, cudaFuncAttributeMaxDynamicSharedMemorySize, GEMM_SMEM);
    cudaFuncSetAttribute(gemm_tf32_kernel<2>, cudaFuncAttributeMaxDynamicSharedMemorySize, GEMM_SMEM);

    // degrees + norms (iteration-invariant)
    cudaMemsetAsync(base + O_DEG_PV, 0, (2 * V + 2 * C) * sizeof(float));
    deg_kernel<<<(unsigned)((EP + 255) / 256), 256>>>(v_edge, c_edge, p_sel, (int)EP, degPV, degPC, pv, pc);
    deg_kernel<<<(unsigned)((EN + 255) / 256), 256>>>(v_edge, c_edge, n_sel, (int)EN, degNV, degNC, nv, nc);
    norm_kernel<<<(unsigned)((EP + 255) / 256), 256>>>(pv, pc, degPV, degPC, pnorm, (int)EP);
    norm_kernel<<<(unsigned)((EN + 255) / 256), 256>>>(nv, nc, degNV, degNC, nnorm, (int)EN);

    // iteration 0 embeddings straight into the output stacks
    cudaMemcpyAsync(OV, v_emb0, V * DIMV * sizeof(float), cudaMemcpyDeviceToDevice);
    cudaMemcpyAsync(OC, c_emb0, C * DIMV * sizeof(float), cudaMemcpyDeviceToDevice);

    for (int it = 0; it < NITER; it++) {
        const float* Vc = OV + (long)it * V * DIMV;
        const float* Cc = OC + (long)it * C * DIMV;
        float* Vn = OV + (long)(it + 1) * V * DIMV;
        float* Cn = OC + (long)(it + 1) * C * DIMV;

        // 4 message MLPs on node features (old embeddings)
        gemm(0, Vc, W1 + 0 * 16384, b1 + 0 * 128, hid, V);
        gemm(1, hid, W2 + 0 * 16384, b2 + 0 * 128, msgPV2C, V);
        gemm(0, Vc, W1 + 1 * 16384, b1 + 1 * 128, hid, V);
        gemm(1, hid, W2 + 1 * 16384, b2 + 1 * 128, msgNV2C, V);
        gemm(0, Cc, W1 + 2 * 16384, b1 + 2 * 128, hid, C);
        gemm(1, hid, W2 + 2 * 16384, b2 + 2 * 128, msgPC2V, C);
        gemm(0, Cc, W1 + 3 * 16384, b1 + 3 * 128, hid, C);
        gemm(1, hid, W2 + 3 * 16384, b2 + 3 * 128, msgNC2V, C);

        // zero aggregate buffers, scatter both edge sets
        cudaMemsetAsync(aggPC, 0, (2 * C + 2 * V) * DIMV * sizeof(float));
        scatter_kernel<<<(unsigned)(EP / 8), 256>>>(pv, pc, msgPV2C, msgPC2V, pnorm, aggPC, aggPV, (int)EP);
        scatter_kernel<<<(unsigned)(EN / 8), 256>>>(nv, nc, msgNV2C, msgNC2V, nnorm, aggNC, aggNV, (int)EN);

        // clause update: concat(Cc, aggPC, aggNC) @ cW + cB  (3 chained K=128 passes)
        gemm(1, Cc,    cW + 0 * 16384, cB, Cn, C);
        gemm(2, aggPC, cW + 1 * 16384, nullptr, Cn, C);
        gemm(2, aggNC, cW + 2 * 16384, nullptr, Cn, C);

        // variable update
        gemm(1, Vc,    vW + 0 * 16384, vB, Vn, V);
        gemm(2, aggPV, vW + 1 * 16384, nullptr, Vn, V);
        gemm(2, aggNV, vW + 2 * 16384, nullptr, Vn, V);
    }
}

// round 4
// speedup vs baseline: 2.7470x; 2.7470x over previous
#include <cuda_runtime.h>
#include <math.h>
#include <stdint.h>

#define DIMV 128

static const long V  = 50000;
static const long C  = 150000;
static const long EP = 200000;
static const long EN = 200000;
static const int  NITER = 4;

// ---------------- scratch layout (floats) ----------------
#define O_MSG_PV2C 0L
#define O_MSG_NV2C (O_MSG_PV2C + V*DIMV)
#define O_MSG_PC2V (O_MSG_NV2C + V*DIMV)
#define O_MSG_NC2V (O_MSG_PC2V + C*DIMV)
#define O_HID      (O_MSG_NC2V + C*DIMV)
#define O_AGG_PC   (O_HID + C*DIMV)
#define O_AGG_NC   (O_AGG_PC + C*DIMV)
#define O_AGG_PV   (O_AGG_NC + C*DIMV)
#define O_AGG_NV   (O_AGG_PV + V*DIMV)
#define O_DEG_PV   (O_AGG_NV + V*DIMV)
#define O_DEG_NV   (O_DEG_PV + V)
#define O_DEG_PC   (O_DEG_NV + V)
#define O_DEG_NC   (O_DEG_PC + C)
#define O_PNORM    (O_DEG_NC + C)
#define O_NNORM    (O_PNORM + EP)
#define O_IDX      (O_NNORM + EN)
#define O_WFRAG    (O_IDX + 2*EP + 2*EN)
#define SCRATCH_TOTAL (O_WFRAG + 14L*16384)

__device__ float g_scratch[SCRATCH_TOTAL];

// ---------------- small kernels ----------------

__global__ void deg_kernel(const int* __restrict__ ev, const int* __restrict__ ec,
                           const int* __restrict__ sel, int nE,
                           float* __restrict__ degv, float* __restrict__ degc,
                           int* __restrict__ outv, int* __restrict__ outc)
{
    int e = blockIdx.x * blockDim.x + threadIdx.x;
    if (e >= nE) return;
    int ed = sel[e];
    int v = ev[ed], c = ec[ed];
    outv[e] = v; outc[e] = c;
    atomicAdd(&degv[v], 1.0f);
    atomicAdd(&degc[c], 1.0f);
}

__global__ void norm_kernel(const int* __restrict__ iv, const int* __restrict__ ic,
                            const float* __restrict__ degv, const float* __restrict__ degc,
                            float* __restrict__ ninv, int nE)
{
    int e = blockIdx.x * blockDim.x + threadIdx.x;
    if (e >= nE) return;
    float dv = fmaxf(degv[iv[e]], 1.0f);
    float dc = fmaxf(degc[ic[e]], 1.0f);
    ninv[e] = 1.0f / (sqrtf(dv) * sqrtf(dc));
}

__device__ __forceinline__ void red_add_v4(float* addr, float4 v)
{
    asm volatile("red.global.add.v4.f32 [%0], {%1,%2,%3,%4};"
                 :: "l"(addr), "f"(v.x), "f"(v.y), "f"(v.z), "f"(v.w) : "memory");
}
__device__ __forceinline__ void red_add_v2(float* addr, float a, float b)
{
    asm volatile("red.global.add.v2.f32 [%0], {%1,%2};"
                 :: "l"(addr), "f"(a), "f"(b) : "memory");
}

// one warp per edge: gather msg rows for both directions, scale, vector-reduce.
__global__ void scatter_kernel(const int* __restrict__ si, const int* __restrict__ di,
                               const float* __restrict__ msgS, const float* __restrict__ msgD,
                               const float* __restrict__ ninv,
                               float* __restrict__ aggD, float* __restrict__ aggS, int nE)
{
    int w = (blockIdx.x * blockDim.x + threadIdx.x) >> 5;
    int lane = threadIdx.x & 31;
    if (w >= nE) return;
    int s = si[w];
    int d = di[w];
    float nv = ninv[w];
    float4 a = ((const float4*)(msgS + (long)s * DIMV))[lane];
    float4 b = ((const float4*)(msgD + (long)d * DIMV))[lane];
    a.x *= nv; a.y *= nv; a.z *= nv; a.w *= nv;
    b.x *= nv; b.y *= nv; b.z *= nv; b.w *= nv;
    red_add_v4(aggD + (long)d * DIMV + lane * 4, a);
    red_add_v4(aggS + (long)s * DIMV + lane * 4, b);
}

// ---------------- TF32 tensor-core GEMM ----------------

__device__ __forceinline__ uint32_t f2tf32(float f)
{
    uint32_t t;
    asm("cvt.rna.tf32.f32 %0, %1;" : "=r"(t) : "f"(f));
    return t;
}

__device__ __forceinline__ void mma_tf32(float* c, const uint32_t* a, uint32_t b0, uint32_t b1)
{
    asm volatile("mma.sync.aligned.m16n8k8.row.col.f32.tf32.tf32.f32 "
                 "{%0,%1,%2,%3}, {%4,%5,%6,%7}, {%8,%9}, {%0,%1,%2,%3};"
                 : "+f"(c[0]), "+f"(c[1]), "+f"(c[2]), "+f"(c[3])
                 : "r"(a[0]), "r"(a[1]), "r"(a[2]), "r"(a[3]), "r"(b0), "r"(b1));
}

// One-time weight fragment permutation: 14 blocks of [128,128] -> mma B-frag
// layout [ks 16][ntile 16][lane 32][reg 2] as tf32 bits.
__global__ void wprep_kernel(const float* __restrict__ W1, const float* __restrict__ W2,
                             const float* __restrict__ cW, const float* __restrict__ vW,
                             uint32_t* __restrict__ dst)
{
    int blk = blockIdx.x;  // 0..13
    const float* src;
    if (blk < 4)       src = W1 + blk * 16384;
    else if (blk < 8)  src = W2 + (blk - 4) * 16384;
    else if (blk < 11) src = cW + (blk - 8) * 16384;
    else               src = vW + (blk - 11) * 16384;
    uint32_t* d = dst + (long)blk * 16384;
    for (int idx = threadIdx.x; idx < 16384; idx += blockDim.x) {
        int k = idx >> 7, n = idx & 127;
        int ks = k >> 3, kk = k & 7;
        int reg = kk >> 2, klane = kk & 3;
        int ntile = n >> 3, nn = n & 7;
        d[((ks * 16 + ntile) * 32 + nn * 4 + klane) * 2 + reg] = f2tf32(src[idx]);
    }
}

// out[N,128] = X[N,128] @ W[128,128]  (W pre-permuted fragments)
// MODE 0: relu(X@W+bias)   MODE 1: X@W+bias   MODE 2: red.add(out, X@W)
// Persistent grid-stride over 64-row tiles. 256 threads = 8 warps in a 2x4
// grid (warp tile 32x32). smem: Bs (64KB frag copy) + As (row-major pitch-132,
// conflict-free both on STS.128 store and LDS.32 fragment gather).
#define PITCH 132
#define GEMM_SMEM ((16384 + 64 * PITCH) * 4)
#define GGRID 296

template<int MODE>
__global__ __launch_bounds__(256)
void gemm_tf32_kernel(const float* __restrict__ X, const uint32_t* __restrict__ Wfrag,
                      const float* __restrict__ bias, float* __restrict__ out, int N)
{
    extern __shared__ uint32_t sm[];
    uint32_t* Bs = sm;              // 16384 words
    uint32_t* As = sm + 16384;      // 64*PITCH words

    const int tid = threadIdx.x;
    const int w = tid >> 5, lane = tid & 31;
    const int wr = w >> 2, wc = w & 3;
    const int q = lane >> 2, t = lane & 3;

    // one-time Bs copy (linear, conflict-free)
    {
        const uint4* src = (const uint4*)Wfrag;
        uint4* dst = (uint4*)Bs;
        #pragma unroll
        for (int i = 0; i < 16; i++) dst[tid + i * 256] = src[tid + i * 256];
    }

    float2 bv[4];
    if (MODE != 2) {
        #pragma unroll
        for (int ni = 0; ni < 4; ni++)
            bv[ni] = *(const float2*)(bias + wc * 32 + ni * 8 + t * 2);
    }
    __syncthreads();

    const int ntiles = (N + 63) >> 6;
    for (int tile = blockIdx.x; tile < ntiles; tile += gridDim.x) {
        const long row0 = (long)tile << 6;

        // X tile -> As (tf32-converted, row-major pitch 132)
        #pragma unroll
        for (int i = 0; i < 8; i++) {
            int idx = tid + i * 256;
            int r = idx >> 5, c4 = idx & 31;
            long rr = row0 + r;
            float4 v = make_float4(0.f, 0.f, 0.f, 0.f);
            if (rr < N) v = ((const float4*)X)[rr * 32 + c4];
            uint4 u;
            u.x = f2tf32(v.x); u.y = f2tf32(v.y);
            u.z = f2tf32(v.z); u.w = f2tf32(v.w);
            *(uint4*)(As + r * PITCH + c4 * 4) = u;
        }
        __syncthreads();

        float acc[2][4][4] = {};
        const uint32_t* A0 = As + (wr * 32 + q) * PITCH + t;

        #pragma unroll
        for (int ks = 0; ks < 16; ks++) {
            const int k0 = ks * 8;
            uint32_t a[2][4];
            #pragma unroll
            for (int mi = 0; mi < 2; mi++) {
                const uint32_t* Ap = A0 + mi * 16 * PITCH;
                a[mi][0] = Ap[k0];
                a[mi][1] = Ap[8 * PITCH + k0];
                a[mi][2] = Ap[k0 + 4];
                a[mi][3] = Ap[8 * PITCH + k0 + 4];
            }
            #pragma unroll
            for (int ni = 0; ni < 4; ni++) {
                uint2 b = ((const uint2*)Bs)[(ks * 16 + wc * 4 + ni) * 32 + lane];
                mma_tf32(acc[0][ni], a[0], b.x, b.y);
                mma_tf32(acc[1][ni], a[1], b.x, b.y);
            }
        }

        // epilogue
        #pragma unroll
        for (int mi = 0; mi < 2; mi++) {
            #pragma unroll
            for (int h = 0; h < 2; h++) {
                long rg = row0 + wr * 32 + mi * 16 + h * 8 + q;
                if (rg < N) {
                    #pragma unroll
                    for (int ni = 0; ni < 4; ni++) {
                        int colg = wc * 32 + ni * 8 + t * 2;
                        float o0 = acc[mi][ni][h * 2 + 0];
                        float o1 = acc[mi][ni][h * 2 + 1];
                        if (MODE == 2) {
                            red_add_v2(out + rg * DIMV + colg, o0, o1);
                        } else {
                            o0 += bv[ni].x; o1 += bv[ni].y;
                            if (MODE == 0) { o0 = fmaxf(o0, 0.f); o1 = fmaxf(o1, 0.f); }
                            *(float2*)(out + rg * DIMV + colg) = make_float2(o0, o1);
                        }
                    }
                }
            }
        }
        __syncthreads();
    }
}

// ---------------- host side ----------------

static void gemm(int mode, const float* X, const uint32_t* Wfrag, const float* bias,
                 float* out, long N)
{
    if (mode == 0)      gemm_tf32_kernel<0><<<GGRID, 256, GEMM_SMEM>>>(X, Wfrag, bias, out, (int)N);
    else if (mode == 1) gemm_tf32_kernel<1><<<GGRID, 256, GEMM_SMEM>>>(X, Wfrag, bias, out, (int)N);
    else                gemm_tf32_kernel<2><<<GGRID, 256, GEMM_SMEM>>>(X, Wfrag, bias, out, (int)N);
}

extern "C" void kernel_launch(void* const* d_in, const int* in_sizes, int n_in,
                              void* d_out, int out_size)
{
    const int ofs = n_in - 14;
    const int*   v_edge = (const int*)d_in[ofs + 0];
    const int*   c_edge = (const int*)d_in[ofs + 1];
    const int*   p_sel  = (const int*)d_in[ofs + 2];
    const int*   n_sel  = (const int*)d_in[ofs + 3];
    const float* v_emb0 = (const float*)d_in[ofs + 4];
    const float* c_emb0 = (const float*)d_in[ofs + 5];
    const float* W1     = (const float*)d_in[ofs + 6];
    const float* b1     = (const float*)d_in[ofs + 7];
    const float* W2     = (const float*)d_in[ofs + 8];
    const float* b2     = (const float*)d_in[ofs + 9];
    const float* cW     = (const float*)d_in[ofs + 10];
    const float* cB     = (const float*)d_in[ofs + 11];
    const float* vW     = (const float*)d_in[ofs + 12];
    const float* vB     = (const float*)d_in[ofs + 13];

    float* base = nullptr;
    cudaGetSymbolAddress((void**)&base, g_scratch);

    float* msgPV2C = base + O_MSG_PV2C;
    float* msgNV2C = base + O_MSG_NV2C;
    float* msgPC2V = base + O_MSG_PC2V;
    float* msgNC2V = base + O_MSG_NC2V;
    float* hid     = base + O_HID;
    float* aggPC   = base + O_AGG_PC;
    float* aggNC   = base + O_AGG_NC;
    float* aggPV   = base + O_AGG_PV;
    float* aggNV   = base + O_AGG_NV;
    float* degPV   = base + O_DEG_PV;
    float* degNV   = base + O_DEG_NV;
    float* degPC   = base + O_DEG_PC;
    float* degNC   = base + O_DEG_NC;
    float* pnorm   = base + O_PNORM;
    float* nnorm   = base + O_NNORM;
    int*   pv      = (int*)(base + O_IDX);
    int*   pc      = pv + EP;
    int*   nv      = pc + EP;
    int*   nc      = nv + EN;
    uint32_t* wf   = (uint32_t*)(base + O_WFRAG);

    float* out = (float*)d_out;
    float* OV = out;                    // [5][V][128]
    float* OC = out + 5L * V * DIMV;    // [5][C][128]

    cudaFuncSetAttribute(gemm_tf32_kernel<0>, cudaFuncAttributeMaxDynamicSharedMemorySize, GEMM_SMEM);
    cudaFuncSetAttribute(gemm_tf32_kernel<1>, cudaFuncAttributeMaxDynamicSharedMemorySize, GEMM_SMEM);
    cudaFuncSetAttribute(gemm_tf32_kernel<2>, cudaFuncAttributeMaxDynamicSharedMemorySize, GEMM_SMEM);

    // one-time: weight fragments + degrees + norms
    wprep_kernel<<<14, 256>>>(W1, W2, cW, vW, wf);
    cudaMemsetAsync(base + O_DEG_PV, 0, (2 * V + 2 * C) * sizeof(float));
    deg_kernel<<<(unsigned)((EP + 255) / 256), 256>>>(v_edge, c_edge, p_sel, (int)EP, degPV, degPC, pv, pc);
    deg_kernel<<<(unsigned)((EN + 255) / 256), 256>>>(v_edge, c_edge, n_sel, (int)EN, degNV, degNC, nv, nc);
    norm_kernel<<<(unsigned)((EP + 255) / 256), 256>>>(pv, pc, degPV, degPC, pnorm, (int)EP);
    norm_kernel<<<(unsigned)((EN + 255) / 256), 256>>>(nv, nc, degNV, degNC, nnorm, (int)EN);

    // iteration 0 embeddings straight into the output stacks
    cudaMemcpyAsync(OV, v_emb0, V * DIMV * sizeof(float), cudaMemcpyDeviceToDevice);
    cudaMemcpyAsync(OC, c_emb0, C * DIMV * sizeof(float), cudaMemcpyDeviceToDevice);

    for (int it = 0; it < NITER; it++) {
        const float* Vc = OV + (long)it * V * DIMV;
        const float* Cc = OC + (long)it * C * DIMV;
        float* Vn = OV + (long)(it + 1) * V * DIMV;
        float* Cn = OC + (long)(it + 1) * C * DIMV;

        // 4 message MLPs  (wf blocks: W1[i] -> i, W2[i] -> 4+i)
        gemm(0, Vc, wf + 0L * 16384, b1 + 0 * 128, hid, V);
        gemm(1, hid, wf + 4L * 16384, b2 + 0 * 128, msgPV2C, V);
        gemm(0, Vc, wf + 1L * 16384, b1 + 1 * 128, hid, V);
        gemm(1, hid, wf + 5L * 16384, b2 + 1 * 128, msgNV2C, V);
        gemm(0, Cc, wf + 2L * 16384, b1 + 2 * 128, hid, C);
        gemm(1, hid, wf + 6L * 16384, b2 + 2 * 128, msgPC2V, C);
        gemm(0, Cc, wf + 3L * 16384, b1 + 3 * 128, hid, C);
        gemm(1, hid, wf + 7L * 16384, b2 + 3 * 128, msgNC2V, C);

        // zero aggregate buffers, scatter both edge sets
        cudaMemsetAsync(aggPC, 0, (2 * C + 2 * V) * DIMV * sizeof(float));
        scatter_kernel<<<(unsigned)(EP / 8), 256>>>(pv, pc, msgPV2C, msgPC2V, pnorm, aggPC, aggPV, (int)EP);
        scatter_kernel<<<(unsigned)(EN / 8), 256>>>(nv, nc, msgNV2C, msgNC2V, nnorm, aggNC, aggNV, (int)EN);

        // clause update (cW blocks 8..10)
        gemm(1, Cc,    wf + 8L * 16384, cB, Cn, C);
        gemm(2, aggPC, wf + 9L * 16384, nullptr, Cn, C);
        gemm(2, aggNC, wf + 10L * 16384, nullptr, Cn, C);

        // variable update (vW blocks 11..13)
        gemm(1, Vc,    wf + 11L * 16384, vB, Vn, V);
        gemm(2, aggPV, wf + 12L * 16384, nullptr, Vn, V);
        gemm(2, aggNV, wf + 13L * 16384, nullptr, Vn, V);
    }
}